// round 7
// baseline (speedup 1.0000x reference)
#include <cuda_runtime.h>
#include <math.h>

#define NN 50000
#define EE 800000
#define HH 4
#define DD 32
#define FF 128

// ---------------- scratch (device globals; no allocation allowed) ----------
__device__ float g_feat[NN * FF];   // current layer's transformed features
__device__ float g_hA[NN * FF];     // layer0 output / layer1 input+residual
__device__ float g_hB[NN * FF];     // layer1 output / layer2 input+residual
__device__ float g_el[NN * HH];
__device__ float g_er[NN * HH];
__device__ int   g_rowptr[NN + 1];

// ---------------- packed f32x2 helpers (FFMA2 — ptxas never emits this) ----
__device__ __forceinline__ unsigned long long pack2(float x, float y) {
    unsigned long long r;
    asm("mov.b64 %0, {%1, %2};" : "=l"(r) : "r"(__float_as_uint(x)), "r"(__float_as_uint(y)));
    return r;
}
__device__ __forceinline__ unsigned long long ffma2(unsigned long long a,
                                                    unsigned long long b,
                                                    unsigned long long c) {
    unsigned long long d;
    asm("fma.rn.f32x2 %0, %1, %2, %3;" : "=l"(d) : "l"(a), "l"(b), "l"(c));
    return d;
}

// ---------------- CSR row pointers from sorted dst -------------------------
__global__ void rowptr_kernel(const int* __restrict__ dst) {
    int t = blockIdx.x * blockDim.x + threadIdx.x;
    if (t > NN) return;
    int lo = 0, hi = EE;
    while (lo < hi) {
        int mid = (lo + hi) >> 1;
        if (dst[mid] < t) lo = mid + 1; else hi = mid;
    }
    g_rowptr[t] = lo;
}

// ---------------- GEMM + fused el/er epilogue ------------------------------
// g_feat[N,128] = A[N,128] @ W[128,128]; then
// g_el[n,h] = sum_d feat[n,h*32+d]*al[h*32+d], g_er likewise.
__global__ __launch_bounds__(256, 2) void gemm_kernel(const float* __restrict__ A,
                                                      const float* __restrict__ W,
                                                      const float* __restrict__ al,
                                                      const float* __restrict__ ar) {
    __shared__ float As[32][132];   // 16896 B — reused as redL[128][17] in epilogue
    __shared__ float Ws[32][128];   // 16384 B — reused as redR[128][17] in epilogue

    const int t  = threadIdx.x;
    const int ty = t >> 4;          // 0..15
    const int tx = t & 15;          // 0..15
    const int m0 = ty * 8;
    const int c0 = tx * 8;
    const int rowBase = blockIdx.x * 128;

    unsigned long long acc2[8][4];
#pragma unroll
    for (int i = 0; i < 8; i++)
#pragma unroll
        for (int j = 0; j < 4; j++) acc2[i][j] = 0ull;

    float4 aReg[4], wReg[4];

    // prefetch chunk 0
#pragma unroll
    for (int i = 0; i < 4; i++) {
        int idx = t + i * 256;
        int row = idx >> 3, k4 = idx & 7;
        int gr = rowBase + row;
        aReg[i] = (gr < NN) ? reinterpret_cast<const float4*>(A)[gr * 32 + k4]
                            : make_float4(0.f, 0.f, 0.f, 0.f);
        int k = idx >> 5, j4 = idx & 31;
        wReg[i] = reinterpret_cast<const float4*>(W)[k * 32 + j4];
    }

    for (int kc = 0; kc < 4; ++kc) {
        // store prefetched regs to smem
#pragma unroll
        for (int i = 0; i < 4; i++) {
            int idx = t + i * 256;
            int row = idx >> 3, k4 = idx & 7;
            As[k4 * 4 + 0][row] = aReg[i].x;
            As[k4 * 4 + 1][row] = aReg[i].y;
            As[k4 * 4 + 2][row] = aReg[i].z;
            As[k4 * 4 + 3][row] = aReg[i].w;
            int k = idx >> 5, j4 = idx & 31;
            reinterpret_cast<float4*>(&Ws[k][0])[j4] = wReg[i];
        }
        __syncthreads();

        // issue next chunk's global loads before compute (latency overlap)
        if (kc < 3) {
#pragma unroll
            for (int i = 0; i < 4; i++) {
                int idx = t + i * 256;
                int row = idx >> 3, k4 = idx & 7;
                int gr = rowBase + row;
                aReg[i] = (gr < NN)
                        ? reinterpret_cast<const float4*>(A)[gr * 32 + (kc + 1) * 8 + k4]
                        : make_float4(0.f, 0.f, 0.f, 0.f);
                int k = idx >> 5, j4 = idx & 31;
                wReg[i] = reinterpret_cast<const float4*>(W)[((kc + 1) * 32 + k) * 32 + j4];
            }
        }

#pragma unroll
        for (int k = 0; k < 32; k++) {
            float4 a0 = *reinterpret_cast<const float4*>(&As[k][m0]);
            float4 a1 = *reinterpret_cast<const float4*>(&As[k][m0 + 4]);
            float4 w0 = *reinterpret_cast<const float4*>(&Ws[k][c0]);
            float4 w1 = *reinterpret_cast<const float4*>(&Ws[k][c0 + 4]);
            unsigned long long wp[4];
            wp[0] = pack2(w0.x, w0.y);
            wp[1] = pack2(w0.z, w0.w);
            wp[2] = pack2(w1.x, w1.y);
            wp[3] = pack2(w1.z, w1.w);
            float av[8] = {a0.x, a0.y, a0.z, a0.w, a1.x, a1.y, a1.z, a1.w};
#pragma unroll
            for (int i = 0; i < 8; i++) {
                unsigned long long ap = pack2(av[i], av[i]);
#pragma unroll
                for (int j = 0; j < 4; j++) acc2[i][j] = ffma2(ap, wp[j], acc2[i][j]);
            }
        }
        __syncthreads();
    }

    // ---- unpack accumulators, store feat, compute per-thread el/er partials
    float fv[8][8];
#pragma unroll
    for (int i = 0; i < 8; i++) {
        float2 p0 = *reinterpret_cast<float2*>(&acc2[i][0]);
        float2 p1 = *reinterpret_cast<float2*>(&acc2[i][1]);
        float2 p2 = *reinterpret_cast<float2*>(&acc2[i][2]);
        float2 p3 = *reinterpret_cast<float2*>(&acc2[i][3]);
        fv[i][0] = p0.x; fv[i][1] = p0.y; fv[i][2] = p1.x; fv[i][3] = p1.y;
        fv[i][4] = p2.x; fv[i][5] = p2.y; fv[i][6] = p3.x; fv[i][7] = p3.y;
        int gr = rowBase + m0 + i;
        if (gr < NN) {
            reinterpret_cast<float4*>(g_feat)[(gr * FF + c0) >> 2] =
                make_float4(fv[i][0], fv[i][1], fv[i][2], fv[i][3]);
            reinterpret_cast<float4*>(g_feat)[(gr * FF + c0 + 4) >> 2] =
                make_float4(fv[i][4], fv[i][5], fv[i][6], fv[i][7]);
        }
    }

    float alv[8], arv[8];
#pragma unroll
    for (int j = 0; j < 8; j++) {
        alv[j] = __ldg(&al[c0 + j]);
        arv[j] = __ldg(&ar[c0 + j]);
    }

    // reuse smem: redL/redR[row][tx], stride 17 to dodge bank conflicts
    float* redL = &As[0][0];   // needs 128*17 = 2176 floats (fits in As)
    float* redR = &Ws[0][0];   // needs 2176 floats (fits in Ws)
#pragma unroll
    for (int i = 0; i < 8; i++) {
        float pl = 0.f, pr = 0.f;
#pragma unroll
        for (int j = 0; j < 8; j++) {
            pl = fmaf(fv[i][j], alv[j], pl);
            pr = fmaf(fv[i][j], arv[j], pr);
        }
        redL[(m0 + i) * 17 + tx] = pl;
        redR[(m0 + i) * 17 + tx] = pr;
    }
    __syncthreads();

    // 512 (row, head) outputs; 256 threads -> 2 each; sum 4 tx partials
#pragma unroll
    for (int o = 0; o < 2; o++) {
        int outIdx = t + o * 256;          // 0..511
        int row  = outIdx >> 2;            // 0..127
        int head = outIdx & 3;             // 0..3
        int gr = rowBase + row;
        if (gr < NN) {
            int base = row * 17 + head * 4;
            float sl = (redL[base] + redL[base + 1]) + (redL[base + 2] + redL[base + 3]);
            float sr = (redR[base] + redR[base + 1]) + (redR[base + 2] + redR[base + 3]);
            g_el[gr * HH + head] = sl;
            g_er[gr * HH + head] = sr;
        }
    }
}

// ---------------- edge aggregation: online softmax over incoming edges -----
// 2 nodes per 256-thread block; within a node-half: warp h = head h, lane = d.
// Batch-max-then-exp: one rescale per chunk, 8 independent pipelined expfs.
// MODE 0: no residual, ELU, write [N,128]
// MODE 1: residual,   ELU, write [N,128]
// MODE 2: residual, no act, head-mean -> write [N,32]
template <int MODE>
__global__ __launch_bounds__(256) void edge_kernel(const int* __restrict__ src,
                                                   const float* __restrict__ hres,
                                                   float* __restrict__ out) {
    const int tAll = threadIdx.x;
    const int half = tAll >> 7;               // 0 or 1 -> which node
    const int t    = tAll & 127;              // thread-in-node
    const int n    = blockIdx.x * 2 + half;
    const int h    = t >> 5, lane = t & 31;
    const bool live = (n < NN);

    int start = 0, end = 0;
    float ern = 0.f;
    if (live) {
        start = g_rowptr[n];
        end   = g_rowptr[n + 1];
        ern   = g_er[n * HH + h];
    }
    const float* fbase = g_feat + h * DD + lane;

    float m = -INFINITY, s = 0.f, acc = 0.f;

    const int CH = 8;
    for (int j0 = start; j0 < end; j0 += CH) {
        int   svb[CH];
        float eb [CH];
        float fb [CH];
#pragma unroll
        for (int u = 0; u < CH; ++u) {
            int jj = j0 + u;
            svb[u] = (jj < end) ? __ldg(&src[jj]) : 0;
        }
#pragma unroll
        for (int u = 0; u < CH; ++u) {
            eb[u] = __ldg(&g_el[svb[u] * HH + h]);
            fb[u] = __ldg(&fbase[svb[u] * FF]);
        }
        // leaky-relu logits; OOB lanes -> -inf (exp -> 0, contributes nothing)
#pragma unroll
        for (int u = 0; u < CH; ++u) {
            float e = eb[u] + ern;
            e = fmaxf(e, 0.2f * e);            // leaky ReLU (exact select)
            eb[u] = (j0 + u < end) ? e : -INFINITY;
        }
        // batch max (3-level tree)
        float mb01 = fmaxf(eb[0], eb[1]), mb23 = fmaxf(eb[2], eb[3]);
        float mb45 = fmaxf(eb[4], eb[5]), mb67 = fmaxf(eb[6], eb[7]);
        float mb = fmaxf(fmaxf(mb01, mb23), fmaxf(mb45, mb67));
        if (mb > m) {
            float c = __expf(m - mb);          // m = -inf first time -> c = 0
            s   *= c;
            acc *= c;
            m = mb;
        }
        // 8 independent expfs (MUFU pipelined) + independent FMAs
        float p[CH];
#pragma unroll
        for (int u = 0; u < CH; ++u) p[u] = __expf(eb[u] - m);
#pragma unroll
        for (int u = 0; u < CH; ++u) {
            s   += p[u];
            acc  = fmaf(p[u], fb[u], acc);
        }
    }

    float v = (end > start) ? (acc / s) : 0.f;
    if (MODE >= 1) { if (live) v += hres[n * FF + t]; }
    if (MODE <= 1) v = (v > 0.f) ? v : (__expf(v) - 1.f);   // ELU

    if (MODE == 2) {
        __shared__ float red[2][FF];
        red[half][t] = v;
        __syncthreads();                       // all 256 threads reach this
        if (live && t < DD) {
            out[n * DD + t] = 0.25f * (red[half][t] + red[half][DD + t] +
                                       red[half][2 * DD + t] + red[half][3 * DD + t]);
        }
    } else {
        if (live) out[n * FF + t] = v;
    }
}

// ---------------- host launch ----------------------------------------------
extern "C" void kernel_launch(void* const* d_in, const int* in_sizes, int n_in,
                              void* d_out, int out_size) {
    const float* x   = (const float*)d_in[0];
    const int*   src = (const int*)  d_in[1];
    const int*   dst = (const int*)  d_in[2];
    const float* W0  = (const float*)d_in[3];
    const float* al0 = (const float*)d_in[4];
    const float* ar0 = (const float*)d_in[5];
    const float* W1  = (const float*)d_in[6];
    const float* al1 = (const float*)d_in[7];
    const float* ar1 = (const float*)d_in[8];
    const float* W2  = (const float*)d_in[9];
    const float* al2 = (const float*)d_in[10];
    const float* ar2 = (const float*)d_in[11];
    float* out = (float*)d_out;

    float *hA = nullptr, *hB = nullptr;
    cudaGetSymbolAddress((void**)&hA, g_hA);
    cudaGetSymbolAddress((void**)&hB, g_hB);

    const int gemmBlocks = (NN + 127) / 128;
    const int edgeBlocks = (NN + 1) / 2;

    rowptr_kernel<<<(NN + 1 + 255) / 256, 256>>>(dst);

    // Layer 0: feat = x @ W0 ; no residual ; ELU -> hA
    gemm_kernel<<<gemmBlocks, 256>>>(x, W0, al0, ar0);
    edge_kernel<0><<<edgeBlocks, 256>>>(src, nullptr, hA);

    // Layer 1: feat = hA @ W1 ; residual hA ; ELU -> hB
    gemm_kernel<<<gemmBlocks, 256>>>(hA, W1, al1, ar1);
    edge_kernel<1><<<edgeBlocks, 256>>>(src, hA, hB);

    // Layer 2: feat = hB @ W2 ; residual hB ; no act ; head-mean -> out [N,32]
    gemm_kernel<<<gemmBlocks, 256>>>(hB, W2, al2, ar2);
    edge_kernel<2><<<edgeBlocks, 256>>>(src, hB, out);
}

// round 12
// speedup vs baseline: 1.1890x; 1.1890x over previous
#include <cuda_runtime.h>
#include <math.h>

#define NN 50000
#define EE 800000
#define HH 4
#define DD 32
#define FF 128

// ---------------- scratch (device globals; no allocation allowed) ----------
__device__ float g_feat[NN * FF];   // current layer's transformed features
__device__ float g_hA[NN * FF];     // layer0 output / layer1 input+residual
__device__ float g_hB[NN * FF];     // layer1 output / layer2 input+residual
__device__ float g_el[NN * HH];
__device__ float g_er[NN * HH];
__device__ int   g_rowptr[NN + 1];

// ---------------- packed f32x2 helpers (FFMA2 — ptxas never emits this) ----
__device__ __forceinline__ unsigned long long pack2(float x, float y) {
    unsigned long long r;
    asm("mov.b64 %0, {%1, %2};" : "=l"(r) : "r"(__float_as_uint(x)), "r"(__float_as_uint(y)));
    return r;
}
__device__ __forceinline__ unsigned long long ffma2(unsigned long long a,
                                                    unsigned long long b,
                                                    unsigned long long c) {
    unsigned long long d;
    asm("fma.rn.f32x2 %0, %1, %2, %3;" : "=l"(d) : "l"(a), "l"(b), "l"(c));
    return d;
}

// ---------------- CSR row pointers from sorted dst -------------------------
__global__ void rowptr_kernel(const int* __restrict__ dst) {
    int t = blockIdx.x * blockDim.x + threadIdx.x;
    if (t > NN) return;
    int lo = 0, hi = EE;
    while (lo < hi) {
        int mid = (lo + hi) >> 1;
        if (dst[mid] < t) lo = mid + 1; else hi = mid;
    }
    g_rowptr[t] = lo;
}

// ---------------- GEMM + fused el/er epilogue ------------------------------
// Tile: 128 rows x 64 cols per block (grid.y selects col half). 256 threads,
// 8x4 outputs/thread as 8x2 f32x2 accumulators -> ~half the registers of the
// old 8x8 tile => 3 CTAs/SM (launch_bounds cap). K chunked by 32 with
// global->reg prefetch. After mainloop, As/Ws smem is reused as el/er
// reduction scratch (Ws[32][68] = exactly 128*17 floats).
__global__ __launch_bounds__(256, 3) void gemm_kernel(const float* __restrict__ A,
                                                      const float* __restrict__ W,
                                                      const float* __restrict__ al,
                                                      const float* __restrict__ ar) {
    __shared__ float As[32][132];   // A chunk [k][row]; reused as redL[128][17]
    __shared__ float Ws[32][68];    // W chunk [k][64 cols]; reused as redR[128][17]

    const int t  = threadIdx.x;
    const int ty = t >> 4;              // 0..15
    const int tx = t & 15;              // 0..15
    const int m0 = ty * 8;              // row offset in tile
    const int c0 = tx * 4;              // local col offset (0..60)
    const int rowBase = blockIdx.x * 128;
    const int colBase = blockIdx.y * 64;        // 0 or 64
    const int colBase4 = colBase >> 2;          // in float4 units (0 or 16)

    unsigned long long acc2[8][2];
#pragma unroll
    for (int i = 0; i < 8; i++) { acc2[i][0] = 0ull; acc2[i][1] = 0ull; }

    float4 aReg[4], wReg[2];

    // prefetch chunk 0
#pragma unroll
    for (int i = 0; i < 4; i++) {
        int idx = t + i * 256;          // 0..1023
        int row = idx >> 3, k4 = idx & 7;
        int gr = rowBase + row;
        aReg[i] = (gr < NN) ? reinterpret_cast<const float4*>(A)[gr * 32 + k4]
                            : make_float4(0.f, 0.f, 0.f, 0.f);
    }
#pragma unroll
    for (int i = 0; i < 2; i++) {
        int idx = t + i * 256;          // 0..511
        int k = idx >> 4, j4 = idx & 15;
        wReg[i] = reinterpret_cast<const float4*>(W)[k * 32 + colBase4 + j4];
    }

    for (int kc = 0; kc < 4; ++kc) {
        // store prefetched regs to smem
#pragma unroll
        for (int i = 0; i < 4; i++) {
            int idx = t + i * 256;
            int row = idx >> 3, k4 = idx & 7;
            As[k4 * 4 + 0][row] = aReg[i].x;
            As[k4 * 4 + 1][row] = aReg[i].y;
            As[k4 * 4 + 2][row] = aReg[i].z;
            As[k4 * 4 + 3][row] = aReg[i].w;
        }
#pragma unroll
        for (int i = 0; i < 2; i++) {
            int idx = t + i * 256;
            int k = idx >> 4, j4 = idx & 15;
            reinterpret_cast<float4*>(&Ws[k][0])[j4] = wReg[i];
        }
        __syncthreads();

        // issue next chunk's global loads before compute (latency overlap)
        if (kc < 3) {
#pragma unroll
            for (int i = 0; i < 4; i++) {
                int idx = t + i * 256;
                int row = idx >> 3, k4 = idx & 7;
                int gr = rowBase + row;
                aReg[i] = (gr < NN)
                        ? reinterpret_cast<const float4*>(A)[gr * 32 + (kc + 1) * 8 + k4]
                        : make_float4(0.f, 0.f, 0.f, 0.f);
            }
#pragma unroll
            for (int i = 0; i < 2; i++) {
                int idx = t + i * 256;
                int k = idx >> 4, j4 = idx & 15;
                wReg[i] = reinterpret_cast<const float4*>(W)[((kc + 1) * 32 + k) * 32 + colBase4 + j4];
            }
        }

#pragma unroll
        for (int k = 0; k < 32; k++) {
            float4 a0 = *reinterpret_cast<const float4*>(&As[k][m0]);
            float4 a1 = *reinterpret_cast<const float4*>(&As[k][m0 + 4]);
            float4 w0 = *reinterpret_cast<const float4*>(&Ws[k][c0]);
            unsigned long long wp0 = pack2(w0.x, w0.y);
            unsigned long long wp1 = pack2(w0.z, w0.w);
            float av[8] = {a0.x, a0.y, a0.z, a0.w, a1.x, a1.y, a1.z, a1.w};
#pragma unroll
            for (int i = 0; i < 8; i++) {
                unsigned long long ap = pack2(av[i], av[i]);
                acc2[i][0] = ffma2(ap, wp0, acc2[i][0]);
                acc2[i][1] = ffma2(ap, wp1, acc2[i][1]);
            }
        }
        __syncthreads();
    }

    // ---- unpack accumulators, store feat, compute per-thread el/er partials
    float fv[8][4];
#pragma unroll
    for (int i = 0; i < 8; i++) {
        float2 p0 = *reinterpret_cast<float2*>(&acc2[i][0]);
        float2 p1 = *reinterpret_cast<float2*>(&acc2[i][1]);
        fv[i][0] = p0.x; fv[i][1] = p0.y; fv[i][2] = p1.x; fv[i][3] = p1.y;
        int gr = rowBase + m0 + i;
        if (gr < NN) {
            *reinterpret_cast<float4*>(&g_feat[gr * FF + colBase + c0]) =
                make_float4(fv[i][0], fv[i][1], fv[i][2], fv[i][3]);
        }
    }

    float alv[4], arv[4];
#pragma unroll
    for (int j = 0; j < 4; j++) {
        alv[j] = __ldg(&al[colBase + c0 + j]);
        arv[j] = __ldg(&ar[colBase + c0 + j]);
    }

    // reuse smem as reduction scratch: redL/redR[row*17 + tx]
    float* redL = &As[0][0];   // 128*17 = 2176 floats (As holds 4224)
    float* redR = &Ws[0][0];   // Ws holds exactly 32*68 = 2176 floats
#pragma unroll
    for (int i = 0; i < 8; i++) {
        float pl = 0.f, pr = 0.f;
#pragma unroll
        for (int j = 0; j < 4; j++) {
            pl = fmaf(fv[i][j], alv[j], pl);
            pr = fmaf(fv[i][j], arv[j], pr);
        }
        redL[(m0 + i) * 17 + tx] = pl;
        redR[(m0 + i) * 17 + tx] = pr;
    }
    __syncthreads();

    // 128 rows x 2 local heads = 256 outputs; one per thread.
    // local head hl covers tx in [hl*8, hl*8+8); global head = blockIdx.y*2+hl
    {
        int row = t >> 1;
        int hl  = t & 1;
        int gr  = rowBase + row;
        if (gr < NN) {
            int base = row * 17 + hl * 8;
            float sl = ((redL[base]     + redL[base + 1]) + (redL[base + 2] + redL[base + 3]))
                     + ((redL[base + 4] + redL[base + 5]) + (redL[base + 6] + redL[base + 7]));
            float sr = ((redR[base]     + redR[base + 1]) + (redR[base + 2] + redR[base + 3]))
                     + ((redR[base + 4] + redR[base + 5]) + (redR[base + 6] + redR[base + 7]));
            int ghead = blockIdx.y * 2 + hl;
            g_el[gr * HH + ghead] = sl;
            g_er[gr * HH + ghead] = sr;
        }
    }
}

// ---------------- edge aggregation: warp-per-node online softmax -----------
// One warp per dst node. Lane d holds float4 features [4d..4d+3] of the
// flattened [H*D]=128 row (head = lane>>3). Each edge = ONE coalesced 512B
// LDG.128 warp load. Softmax scalars (m,s) are per-head, redundantly kept by
// the 8 lanes of each head group. No block barriers (shfl-only reduction).
// MODE 0: no residual, ELU, write [N,128]
// MODE 1: residual,   ELU, write [N,128]
// MODE 2: residual, no act, head-mean -> write [N,32]
template <int MODE>
__global__ __launch_bounds__(256) void edge_kernel(const int* __restrict__ src,
                                                   const float* __restrict__ hres,
                                                   float* __restrict__ out) {
    const int wid  = threadIdx.x >> 5;         // warp within block (0..7)
    const int lane = threadIdx.x & 31;
    const int n    = blockIdx.x * 8 + wid;
    if (n >= NN) return;                        // no barriers below -> safe

    const int head  = lane >> 3;                // 0..3
    const int start = __ldg(&g_rowptr[n]);
    const int end   = __ldg(&g_rowptr[n + 1]);
    const float ern = __ldg(&g_er[n * HH + head]);
    const float* fbase = g_feat + lane * 4;
    const float* elh   = g_el + head;           // loop-invariant base

    // Early residual load: in flight across the whole gather loop.
    float4 r = make_float4(0.f, 0.f, 0.f, 0.f);
    if (MODE >= 1) r = *reinterpret_cast<const float4*>(hres + n * FF + lane * 4);

    float m = -INFINITY, s = 0.f;
    float4 acc = make_float4(0.f, 0.f, 0.f, 0.f);

    const int CH = 8;
    for (int j0 = start; j0 < end; j0 += CH) {
        int    svb[CH];
        float  eb [CH];
        float4 fb [CH];
#pragma unroll
        for (int u = 0; u < CH; ++u) {
            int jj = j0 + u;
            svb[u] = (jj < end) ? __ldg(&src[jj]) : 0;
        }
#pragma unroll
        for (int u = 0; u < CH; ++u) {
            eb[u] = __ldg(elh + svb[u] * HH);
            fb[u] = *reinterpret_cast<const float4*>(fbase + svb[u] * FF);
        }
        // leaky-relu logits; OOB lanes -> -inf (exp -> 0, contributes nothing)
#pragma unroll
        for (int u = 0; u < CH; ++u) {
            float e = eb[u] + ern;
            e = fmaxf(e, 0.2f * e);             // leaky ReLU (exact select)
            eb[u] = (j0 + u < end) ? e : -INFINITY;
        }
        // batch max (3-level tree)
        float mb01 = fmaxf(eb[0], eb[1]), mb23 = fmaxf(eb[2], eb[3]);
        float mb45 = fmaxf(eb[4], eb[5]), mb67 = fmaxf(eb[6], eb[7]);
        float mb = fmaxf(fmaxf(mb01, mb23), fmaxf(mb45, mb67));
        if (mb > m) {
            float c = __expf(m - mb);           // m = -inf first time -> c = 0
            s *= c;
            acc.x *= c; acc.y *= c; acc.z *= c; acc.w *= c;
            m = mb;
        }
        // 8 independent expfs (MUFU pipelined) + independent FMAs
        float p[CH];
#pragma unroll
        for (int u = 0; u < CH; ++u) p[u] = __expf(eb[u] - m);
#pragma unroll
        for (int u = 0; u < CH; ++u) {
            s += p[u];
            acc.x = fmaf(p[u], fb[u].x, acc.x);
            acc.y = fmaf(p[u], fb[u].y, acc.y);
            acc.z = fmaf(p[u], fb[u].z, acc.z);
            acc.w = fmaf(p[u], fb[u].w, acc.w);
        }
    }

    float inv = (end > start) ? (1.f / s) : 0.f;
    float4 v = make_float4(acc.x * inv, acc.y * inv, acc.z * inv, acc.w * inv);

    if (MODE >= 1) { v.x += r.x; v.y += r.y; v.z += r.z; v.w += r.w; }
    if (MODE <= 1) {
        v.x = (v.x > 0.f) ? v.x : (__expf(v.x) - 1.f);
        v.y = (v.y > 0.f) ? v.y : (__expf(v.y) - 1.f);
        v.z = (v.z > 0.f) ? v.z : (__expf(v.z) - 1.f);
        v.w = (v.w > 0.f) ? v.w : (__expf(v.w) - 1.f);
    }

    if (MODE == 2) {
        // head-mean: sum across lanes {d, d+8, d+16, d+24} via shfl_xor
#pragma unroll
        for (int o = 8; o <= 16; o <<= 1) {
            v.x += __shfl_xor_sync(0xffffffffu, v.x, o);
            v.y += __shfl_xor_sync(0xffffffffu, v.y, o);
            v.z += __shfl_xor_sync(0xffffffffu, v.z, o);
            v.w += __shfl_xor_sync(0xffffffffu, v.w, o);
        }
        if (lane < 8) {
            float4 o4 = make_float4(0.25f * v.x, 0.25f * v.y, 0.25f * v.z, 0.25f * v.w);
            *reinterpret_cast<float4*>(out + n * DD + lane * 4) = o4;
        }
    } else {
        *reinterpret_cast<float4*>(out + n * FF + lane * 4) = v;
    }
}

// ---------------- host launch ----------------------------------------------
extern "C" void kernel_launch(void* const* d_in, const int* in_sizes, int n_in,
                              void* d_out, int out_size) {
    const float* x   = (const float*)d_in[0];
    const int*   src = (const int*)  d_in[1];
    const int*   dst = (const int*)  d_in[2];
    const float* W0  = (const float*)d_in[3];
    const float* al0 = (const float*)d_in[4];
    const float* ar0 = (const float*)d_in[5];
    const float* W1  = (const float*)d_in[6];
    const float* al1 = (const float*)d_in[7];
    const float* ar1 = (const float*)d_in[8];
    const float* W2  = (const float*)d_in[9];
    const float* al2 = (const float*)d_in[10];
    const float* ar2 = (const float*)d_in[11];
    float* out = (float*)d_out;

    float *hA = nullptr, *hB = nullptr;
    cudaGetSymbolAddress((void**)&hA, g_hA);
    cudaGetSymbolAddress((void**)&hB, g_hB);

    const dim3 gemmGrid((NN + 127) / 128, 2);
    const int edgeBlocks = (NN + 7) / 8;

    rowptr_kernel<<<(NN + 1 + 255) / 256, 256>>>(dst);

    // Layer 0: feat = x @ W0 ; no residual ; ELU -> hA
    gemm_kernel<<<gemmGrid, 256>>>(x, W0, al0, ar0);
    edge_kernel<0><<<edgeBlocks, 256>>>(src, nullptr, hA);

    // Layer 1: feat = hA @ W1 ; residual hA ; ELU -> hB
    gemm_kernel<<<gemmGrid, 256>>>(hA, W1, al1, ar1);
    edge_kernel<1><<<edgeBlocks, 256>>>(src, hA, hB);

    // Layer 2: feat = hB @ W2 ; residual hB ; no act ; head-mean -> out [N,32]
    gemm_kernel<<<gemmGrid, 256>>>(hB, W2, al2, ar2);
    edge_kernel<2><<<edgeBlocks, 256>>>(src, hB, out);
}

// round 14
// speedup vs baseline: 1.6767x; 1.4102x over previous
#include <cuda_runtime.h>
#include <math.h>

#define NN 50000
#define EE 800000
#define HH 4
#define DD 32
#define FF 128

// ---------------- scratch (device globals; no allocation allowed) ----------
__device__ float g_feat[NN * FF];   // current layer's transformed features
__device__ float g_hA[NN * FF];     // layer0 output / layer1 input+residual
__device__ float g_hB[NN * FF];     // layer1 output / layer2 input+residual
__device__ float g_el[NN * HH];
__device__ float g_er[NN * HH];
__device__ int   g_rowptr[NN + 1];

// ---------------- packed f32x2 helpers (FFMA2 — ptxas never emits this) ----
__device__ __forceinline__ unsigned long long pack2(float x, float y) {
    unsigned long long r;
    asm("mov.b64 %0, {%1, %2};" : "=l"(r) : "r"(__float_as_uint(x)), "r"(__float_as_uint(y)));
    return r;
}
__device__ __forceinline__ unsigned long long ffma2(unsigned long long a,
                                                    unsigned long long b,
                                                    unsigned long long c) {
    unsigned long long d;
    asm("fma.rn.f32x2 %0, %1, %2, %3;" : "=l"(d) : "l"(a), "l"(b), "l"(c));
    return d;
}

// ---------------- CSR row pointers from sorted dst -------------------------
__global__ void rowptr_kernel(const int* __restrict__ dst) {
    int t = blockIdx.x * blockDim.x + threadIdx.x;
    if (t > NN) return;
    int lo = 0, hi = EE;
    while (lo < hi) {
        int mid = (lo + hi) >> 1;
        if (dst[mid] < t) lo = mid + 1; else hi = mid;
    }
    g_rowptr[t] = lo;
}

// ---------------- GEMM + fused el/er epilogue (R7 version, measured 56us) --
// g_feat[N,128] = A[N,128] @ W[128,128]; then
// g_el[n,h] = sum_d feat[n,h*32+d]*al[h*32+d], g_er likewise.
__global__ __launch_bounds__(256, 2) void gemm_kernel(const float* __restrict__ A,
                                                      const float* __restrict__ W,
                                                      const float* __restrict__ al,
                                                      const float* __restrict__ ar) {
    __shared__ float As[32][132];   // 16896 B — reused as redL[128][17] in epilogue
    __shared__ float Ws[32][128];   // 16384 B — reused as redR[128][17] in epilogue

    const int t  = threadIdx.x;
    const int ty = t >> 4;          // 0..15
    const int tx = t & 15;          // 0..15
    const int m0 = ty * 8;
    const int c0 = tx * 8;
    const int rowBase = blockIdx.x * 128;

    unsigned long long acc2[8][4];
#pragma unroll
    for (int i = 0; i < 8; i++)
#pragma unroll
        for (int j = 0; j < 4; j++) acc2[i][j] = 0ull;

    float4 aReg[4], wReg[4];

    // prefetch chunk 0
#pragma unroll
    for (int i = 0; i < 4; i++) {
        int idx = t + i * 256;
        int row = idx >> 3, k4 = idx & 7;
        int gr = rowBase + row;
        aReg[i] = (gr < NN) ? reinterpret_cast<const float4*>(A)[gr * 32 + k4]
                            : make_float4(0.f, 0.f, 0.f, 0.f);
        int k = idx >> 5, j4 = idx & 31;
        wReg[i] = reinterpret_cast<const float4*>(W)[k * 32 + j4];
    }

    for (int kc = 0; kc < 4; ++kc) {
        // store prefetched regs to smem
#pragma unroll
        for (int i = 0; i < 4; i++) {
            int idx = t + i * 256;
            int row = idx >> 3, k4 = idx & 7;
            As[k4 * 4 + 0][row] = aReg[i].x;
            As[k4 * 4 + 1][row] = aReg[i].y;
            As[k4 * 4 + 2][row] = aReg[i].z;
            As[k4 * 4 + 3][row] = aReg[i].w;
            int k = idx >> 5, j4 = idx & 31;
            reinterpret_cast<float4*>(&Ws[k][0])[j4] = wReg[i];
        }
        __syncthreads();

        // issue next chunk's global loads before compute (latency overlap)
        if (kc < 3) {
#pragma unroll
            for (int i = 0; i < 4; i++) {
                int idx = t + i * 256;
                int row = idx >> 3, k4 = idx & 7;
                int gr = rowBase + row;
                aReg[i] = (gr < NN)
                        ? reinterpret_cast<const float4*>(A)[gr * 32 + (kc + 1) * 8 + k4]
                        : make_float4(0.f, 0.f, 0.f, 0.f);
                int k = idx >> 5, j4 = idx & 31;
                wReg[i] = reinterpret_cast<const float4*>(W)[((kc + 1) * 32 + k) * 32 + j4];
            }
        }

#pragma unroll
        for (int k = 0; k < 32; k++) {
            float4 a0 = *reinterpret_cast<const float4*>(&As[k][m0]);
            float4 a1 = *reinterpret_cast<const float4*>(&As[k][m0 + 4]);
            float4 w0 = *reinterpret_cast<const float4*>(&Ws[k][c0]);
            float4 w1 = *reinterpret_cast<const float4*>(&Ws[k][c0 + 4]);
            unsigned long long wp[4];
            wp[0] = pack2(w0.x, w0.y);
            wp[1] = pack2(w0.z, w0.w);
            wp[2] = pack2(w1.x, w1.y);
            wp[3] = pack2(w1.z, w1.w);
            float av[8] = {a0.x, a0.y, a0.z, a0.w, a1.x, a1.y, a1.z, a1.w};
#pragma unroll
            for (int i = 0; i < 8; i++) {
                unsigned long long ap = pack2(av[i], av[i]);
#pragma unroll
                for (int j = 0; j < 4; j++) acc2[i][j] = ffma2(ap, wp[j], acc2[i][j]);
            }
        }
        __syncthreads();
    }

    // ---- unpack accumulators, store feat, compute per-thread el/er partials
    float fv[8][8];
#pragma unroll
    for (int i = 0; i < 8; i++) {
        float2 p0 = *reinterpret_cast<float2*>(&acc2[i][0]);
        float2 p1 = *reinterpret_cast<float2*>(&acc2[i][1]);
        float2 p2 = *reinterpret_cast<float2*>(&acc2[i][2]);
        float2 p3 = *reinterpret_cast<float2*>(&acc2[i][3]);
        fv[i][0] = p0.x; fv[i][1] = p0.y; fv[i][2] = p1.x; fv[i][3] = p1.y;
        fv[i][4] = p2.x; fv[i][5] = p2.y; fv[i][6] = p3.x; fv[i][7] = p3.y;
        int gr = rowBase + m0 + i;
        if (gr < NN) {
            reinterpret_cast<float4*>(g_feat)[(gr * FF + c0) >> 2] =
                make_float4(fv[i][0], fv[i][1], fv[i][2], fv[i][3]);
            reinterpret_cast<float4*>(g_feat)[(gr * FF + c0 + 4) >> 2] =
                make_float4(fv[i][4], fv[i][5], fv[i][6], fv[i][7]);
        }
    }

    float alv[8], arv[8];
#pragma unroll
    for (int j = 0; j < 8; j++) {
        alv[j] = __ldg(&al[c0 + j]);
        arv[j] = __ldg(&ar[c0 + j]);
    }

    // reuse smem: redL/redR[row][tx], stride 17 to dodge bank conflicts
    float* redL = &As[0][0];   // needs 128*17 = 2176 floats (fits in As)
    float* redR = &Ws[0][0];   // needs 2176 floats (fits in Ws)
#pragma unroll
    for (int i = 0; i < 8; i++) {
        float pl = 0.f, pr = 0.f;
#pragma unroll
        for (int j = 0; j < 8; j++) {
            pl = fmaf(fv[i][j], alv[j], pl);
            pr = fmaf(fv[i][j], arv[j], pr);
        }
        redL[(m0 + i) * 17 + tx] = pl;
        redR[(m0 + i) * 17 + tx] = pr;
    }
    __syncthreads();

    // 512 (row, head) outputs; 256 threads -> 2 each; sum 4 tx partials
#pragma unroll
    for (int o = 0; o < 2; o++) {
        int outIdx = t + o * 256;          // 0..511
        int row  = outIdx >> 2;            // 0..127
        int head = outIdx & 3;             // 0..3
        int gr = rowBase + row;
        if (gr < NN) {
            int base = row * 17 + head * 4;
            float sl = (redL[base] + redL[base + 1]) + (redL[base + 2] + redL[base + 3]);
            float sr = (redR[base] + redR[base + 1]) + (redR[base + 2] + redR[base + 3]);
            g_el[gr * HH + head] = sl;
            g_er[gr * HH + head] = sr;
        }
    }
}

// ---------------- edge aggregation: warp-per-node online softmax -----------
// One warp per dst node. Lane d holds float4 features [4d..4d+3] of the
// flattened [H*D]=128 row (head = lane>>3). Each edge = ONE coalesced 512B
// LDG.128 warp load. OOB edge slots are now warp-uniformly branched around:
// NO phantom loads of node 0's row (was ~22% wasted gather traffic).
// MODE 0: no residual, ELU, write [N,128]
// MODE 1: residual,   ELU, write [N,128]
// MODE 2: residual, no act, head-mean -> write [N,32]
template <int MODE>
__global__ __launch_bounds__(256) void edge_kernel(const int* __restrict__ src,
                                                   const float* __restrict__ hres,
                                                   float* __restrict__ out) {
    const int wid  = threadIdx.x >> 5;         // warp within block (0..7)
    const int lane = threadIdx.x & 31;
    const int n    = blockIdx.x * 8 + wid;
    if (n >= NN) return;                        // no barriers below -> safe

    const int head  = lane >> 3;                // 0..3
    const int start = __ldg(&g_rowptr[n]);
    const int end   = __ldg(&g_rowptr[n + 1]);
    const float ern = __ldg(&g_er[n * HH + head]);
    const float* fbase = g_feat + lane * 4;
    const float* elh   = g_el + head;           // loop-invariant base

    // Early residual load: in flight across the whole gather loop.
    float4 r = make_float4(0.f, 0.f, 0.f, 0.f);
    if (MODE >= 1) r = *reinterpret_cast<const float4*>(hres + n * FF + lane * 4);

    float m = -INFINITY, s = 0.f;
    float4 acc = make_float4(0.f, 0.f, 0.f, 0.f);

    const int CH = 8;
    for (int j0 = start; j0 < end; j0 += CH) {
        const int nv = end - j0;                // valid edges this chunk (>=1)
        int    svb[CH];
        float  eb [CH];
        float4 fb [CH];
        // u < nv is warp-uniform -> uniform branch; OOB slots issue NO loads
#pragma unroll
        for (int u = 0; u < CH; ++u)
            svb[u] = (u < nv) ? __ldg(&src[j0 + u]) : 0;
#pragma unroll
        for (int u = 0; u < CH; ++u) {
            if (u < nv) {
                eb[u] = __ldg(elh + svb[u] * HH);
                fb[u] = *reinterpret_cast<const float4*>(fbase + svb[u] * FF);
            } else {
                eb[u] = -INFINITY;              // exp -> 0
                fb[u] = make_float4(0.f, 0.f, 0.f, 0.f);
            }
        }
        // leaky-relu logits (valid slots only; OOB stay -inf)
#pragma unroll
        for (int u = 0; u < CH; ++u) {
            if (u < nv) {
                float e = eb[u] + ern;
                eb[u] = fmaxf(e, 0.2f * e);     // leaky ReLU (exact select)
            }
        }
        // batch max (3-level tree)
        float mb01 = fmaxf(eb[0], eb[1]), mb23 = fmaxf(eb[2], eb[3]);
        float mb45 = fmaxf(eb[4], eb[5]), mb67 = fmaxf(eb[6], eb[7]);
        float mb = fmaxf(fmaxf(mb01, mb23), fmaxf(mb45, mb67));
        if (mb > m) {
            float c = __expf(m - mb);           // m = -inf first time -> c = 0
            s *= c;
            acc.x *= c; acc.y *= c; acc.z *= c; acc.w *= c;
            m = mb;
        }
        // 8 independent expfs (MUFU pipelined) + independent FMAs
        float p[CH];
#pragma unroll
        for (int u = 0; u < CH; ++u) p[u] = __expf(eb[u] - m);
#pragma unroll
        for (int u = 0; u < CH; ++u) {
            s += p[u];
            acc.x = fmaf(p[u], fb[u].x, acc.x);
            acc.y = fmaf(p[u], fb[u].y, acc.y);
            acc.z = fmaf(p[u], fb[u].z, acc.z);
            acc.w = fmaf(p[u], fb[u].w, acc.w);
        }
    }

    float inv = (end > start) ? (1.f / s) : 0.f;
    float4 v = make_float4(acc.x * inv, acc.y * inv, acc.z * inv, acc.w * inv);

    if (MODE >= 1) { v.x += r.x; v.y += r.y; v.z += r.z; v.w += r.w; }
    if (MODE <= 1) {
        v.x = (v.x > 0.f) ? v.x : (__expf(v.x) - 1.f);
        v.y = (v.y > 0.f) ? v.y : (__expf(v.y) - 1.f);
        v.z = (v.z > 0.f) ? v.z : (__expf(v.z) - 1.f);
        v.w = (v.w > 0.f) ? v.w : (__expf(v.w) - 1.f);
    }

    if (MODE == 2) {
        // head-mean: sum across lanes {d, d+8, d+16, d+24} via shfl_xor
#pragma unroll
        for (int o = 8; o <= 16; o <<= 1) {
            v.x += __shfl_xor_sync(0xffffffffu, v.x, o);
            v.y += __shfl_xor_sync(0xffffffffu, v.y, o);
            v.z += __shfl_xor_sync(0xffffffffu, v.z, o);
            v.w += __shfl_xor_sync(0xffffffffu, v.w, o);
        }
        if (lane < 8) {
            float4 o4 = make_float4(0.25f * v.x, 0.25f * v.y, 0.25f * v.z, 0.25f * v.w);
            *reinterpret_cast<float4*>(out + n * DD + lane * 4) = o4;
        }
    } else {
        *reinterpret_cast<float4*>(out + n * FF + lane * 4) = v;
    }
}

// ---------------- host launch ----------------------------------------------
extern "C" void kernel_launch(void* const* d_in, const int* in_sizes, int n_in,
                              void* d_out, int out_size) {
    const float* x   = (const float*)d_in[0];
    const int*   src = (const int*)  d_in[1];
    const int*   dst = (const int*)  d_in[2];
    const float* W0  = (const float*)d_in[3];
    const float* al0 = (const float*)d_in[4];
    const float* ar0 = (const float*)d_in[5];
    const float* W1  = (const float*)d_in[6];
    const float* al1 = (const float*)d_in[7];
    const float* ar1 = (const float*)d_in[8];
    const float* W2  = (const float*)d_in[9];
    const float* al2 = (const float*)d_in[10];
    const float* ar2 = (const float*)d_in[11];
    float* out = (float*)d_out;

    float *hA = nullptr, *hB = nullptr;
    cudaGetSymbolAddress((void**)&hA, g_hA);
    cudaGetSymbolAddress((void**)&hB, g_hB);

    const int gemmBlocks = (NN + 127) / 128;
    const int edgeBlocks = (NN + 7) / 8;

    rowptr_kernel<<<(NN + 1 + 255) / 256, 256>>>(dst);

    // Layer 0: feat = x @ W0 ; no residual ; ELU -> hA
    gemm_kernel<<<gemmBlocks, 256>>>(x, W0, al0, ar0);
    edge_kernel<0><<<edgeBlocks, 256>>>(src, nullptr, hA);

    // Layer 1: feat = hA @ W1 ; residual hA ; ELU -> hB
    gemm_kernel<<<gemmBlocks, 256>>>(hA, W1, al1, ar1);
    edge_kernel<1><<<edgeBlocks, 256>>>(src, hA, hB);

    // Layer 2: feat = hB @ W2 ; residual hB ; no act ; head-mean -> out [N,32]
    gemm_kernel<<<gemmBlocks, 256>>>(hB, W2, al2, ar2);
    edge_kernel<2><<<edgeBlocks, 256>>>(src, hB, out);
}